// round 5
// baseline (speedup 1.0000x reference)
#include <cuda_runtime.h>
#include <cstdint>

#define N_NODES 500000
#define N_EDGES 16000000
#define EPT 8   // edges per thread in edge kernels

// ---------------- scratch (device globals; no allocation allowed) ----------
__device__ int    g_deg [N_NODES];
__device__ float  g_dinv[N_NODES];
__device__ float4 g_g1  [N_NODES];   // dinv-scaled layer-1 features
__device__ float4 g_S1  [N_NODES];   // layer-1 scatter accumulator
__device__ float2 g_g2  [N_NODES];   // dinv-scaled layer-2 features
__device__ float2 g_S2  [N_NODES];   // layer-2 scatter accumulator

// ---------------- vectorized L2 reductions (PTX ISA 8.1, sm_90+) -----------
__device__ __forceinline__ void red_add_v4(float4* addr, float4 v) {
    asm volatile("red.global.add.v4.f32 [%0], {%1, %2, %3, %4};"
                 :: "l"(addr), "f"(v.x), "f"(v.y), "f"(v.z), "f"(v.w)
                 : "memory");
}
__device__ __forceinline__ void red_add_v2(float2* addr, float2 v) {
    asm volatile("red.global.add.v2.f32 [%0], {%1, %2};"
                 :: "l"(addr), "f"(v.x), "f"(v.y)
                 : "memory");
}
// streaming (evict-first) 16B index load
__device__ __forceinline__ int4 ldcs_int4(const int* p) {
    return __ldcs(reinterpret_cast<const int4*>(p));
}

// ---------------- kernels ---------------------------------------------------
__global__ void k_init() {
    int i = blockIdx.x * blockDim.x + threadIdx.x;
    if (i < N_NODES) {
        g_deg[i] = 0;
        g_S1[i]  = make_float4(0.f, 0.f, 0.f, 0.f);
        g_S2[i]  = make_float2(0.f, 0.f);
    }
}

// degree from target (col) indices; EPT edges per thread
__global__ void k_degree(const int* __restrict__ col) {
    int t = blockIdx.x * blockDim.x + threadIdx.x;
    int base = t * EPT;
    if (base >= N_EDGES) return;
    int4 c0 = ldcs_int4(col + base);
    int4 c1 = ldcs_int4(col + base + 4);
    atomicAdd(&g_deg[c0.x], 1);
    atomicAdd(&g_deg[c0.y], 1);
    atomicAdd(&g_deg[c0.z], 1);
    atomicAdd(&g_deg[c0.w], 1);
    atomicAdd(&g_deg[c1.x], 1);
    atomicAdd(&g_deg[c1.y], 1);
    atomicAdd(&g_deg[c1.z], 1);
    atomicAdd(&g_deg[c1.w], 1);
}

// per-node: dinv, h1 = x @ W1, g1 = h1 * dinv
__global__ void k_layer1(const float* __restrict__ x,
                         const float* __restrict__ W1) {
    int i = blockIdx.x * blockDim.x + threadIdx.x;
    if (i >= N_NODES) return;
    float d = rsqrtf((float)g_deg[i] + 1.0f);
    g_dinv[i] = d;
    const float* xr = x + (long long)i * 9;
    float h0 = 0.f, h1 = 0.f, h2 = 0.f, h3 = 0.f;
#pragma unroll
    for (int k = 0; k < 9; ++k) {
        float xv = __ldg(xr + k);
        h0 += xv * __ldg(W1 + k * 4 + 0);
        h1 += xv * __ldg(W1 + k * 4 + 1);
        h2 += xv * __ldg(W1 + k * 4 + 2);
        h3 += xv * __ldg(W1 + k * 4 + 3);
    }
    g_g1[i] = make_float4(h0 * d, h1 * d, h2 * d, h3 * d);
}

// layer-1 edge scatter: S1[col] += g1[row]   (one v4 red per edge)
__global__ void k_scatter1(const int* __restrict__ row,
                           const int* __restrict__ col) {
    int t = blockIdx.x * blockDim.x + threadIdx.x;
    int base = t * EPT;
    if (base >= N_EDGES) return;
    int4 r0 = ldcs_int4(row + base);
    int4 r1 = ldcs_int4(row + base + 4);
    int4 c0 = ldcs_int4(col + base);
    int4 c1 = ldcs_int4(col + base + 4);
    // issue all gathers first (MLP), then reds
    float4 v0 = __ldg(&g_g1[r0.x]);
    float4 v1 = __ldg(&g_g1[r0.y]);
    float4 v2 = __ldg(&g_g1[r0.z]);
    float4 v3 = __ldg(&g_g1[r0.w]);
    float4 v4 = __ldg(&g_g1[r1.x]);
    float4 v5 = __ldg(&g_g1[r1.y]);
    float4 v6 = __ldg(&g_g1[r1.z]);
    float4 v7 = __ldg(&g_g1[r1.w]);
    red_add_v4(&g_S1[c0.x], v0);
    red_add_v4(&g_S1[c0.y], v1);
    red_add_v4(&g_S1[c0.z], v2);
    red_add_v4(&g_S1[c0.w], v3);
    red_add_v4(&g_S1[c1.x], v4);
    red_add_v4(&g_S1[c1.y], v5);
    red_add_v4(&g_S1[c1.z], v6);
    red_add_v4(&g_S1[c1.w], v7);
}

// per-node: t = tanh(dinv*(S1+g1)+b1); h2 = t @ W2; g2 = h2 * dinv
__global__ void k_layer2(const float* __restrict__ W2,
                         const float* __restrict__ b1) {
    int i = blockIdx.x * blockDim.x + threadIdx.x;
    if (i >= N_NODES) return;
    float d  = g_dinv[i];
    float4 s = g_S1[i];
    float4 g = g_g1[i];
    float t0 = tanhf(d * (s.x + g.x) + __ldg(b1 + 0));
    float t1 = tanhf(d * (s.y + g.y) + __ldg(b1 + 1));
    float t2 = tanhf(d * (s.z + g.z) + __ldg(b1 + 2));
    float t3 = tanhf(d * (s.w + g.w) + __ldg(b1 + 3));
    float u0 = t0 * __ldg(W2 + 0) + t1 * __ldg(W2 + 2) + t2 * __ldg(W2 + 4) + t3 * __ldg(W2 + 6);
    float u1 = t0 * __ldg(W2 + 1) + t1 * __ldg(W2 + 3) + t2 * __ldg(W2 + 5) + t3 * __ldg(W2 + 7);
    g_g2[i] = make_float2(u0 * d, u1 * d);
}

// layer-2 edge scatter: S2[col] += g2[row]   (one v2 red per edge)
__global__ void k_scatter2(const int* __restrict__ row,
                           const int* __restrict__ col) {
    int t = blockIdx.x * blockDim.x + threadIdx.x;
    int base = t * EPT;
    if (base >= N_EDGES) return;
    int4 r0 = ldcs_int4(row + base);
    int4 r1 = ldcs_int4(row + base + 4);
    int4 c0 = ldcs_int4(col + base);
    int4 c1 = ldcs_int4(col + base + 4);
    float2 v0 = __ldg(&g_g2[r0.x]);
    float2 v1 = __ldg(&g_g2[r0.y]);
    float2 v2 = __ldg(&g_g2[r0.z]);
    float2 v3 = __ldg(&g_g2[r0.w]);
    float2 v4 = __ldg(&g_g2[r1.x]);
    float2 v5 = __ldg(&g_g2[r1.y]);
    float2 v6 = __ldg(&g_g2[r1.z]);
    float2 v7 = __ldg(&g_g2[r1.w]);
    red_add_v2(&g_S2[c0.x], v0);
    red_add_v2(&g_S2[c0.y], v1);
    red_add_v2(&g_S2[c0.z], v2);
    red_add_v2(&g_S2[c0.w], v3);
    red_add_v2(&g_S2[c1.x], v4);
    red_add_v2(&g_S2[c1.y], v5);
    red_add_v2(&g_S2[c1.z], v6);
    red_add_v2(&g_S2[c1.w], v7);
}

// finalize: out = dinv*(S2+g2) + b2
__global__ void k_final(float2* __restrict__ out,
                        const float* __restrict__ b2) {
    int i = blockIdx.x * blockDim.x + threadIdx.x;
    if (i >= N_NODES) return;
    float d  = g_dinv[i];
    float2 s = g_S2[i];
    float2 g = g_g2[i];
    out[i] = make_float2(d * (s.x + g.x) + __ldg(b2 + 0),
                         d * (s.y + g.y) + __ldg(b2 + 1));
}

// ---------------- launch -----------------------------------------------------
extern "C" void kernel_launch(void* const* d_in, const int* in_sizes, int n_in,
                              void* d_out, int out_size) {
    const float* x  = (const float*)d_in[0];
    const int*   ei = (const int*)d_in[1];     // [2, 16M] int32 (JAX x64 disabled)
    const float* W1 = (const float*)d_in[2];   // [9,4]
    const float* b1 = (const float*)d_in[3];   // [4]
    const float* W2 = (const float*)d_in[4];   // [4,2]
    const float* b2 = (const float*)d_in[5];   // [2]
    float2*      out = (float2*)d_out;         // [N,2] f32

    const int* row = ei;
    const int* col = ei + N_EDGES;

    const int TB = 256;
    const int node_blocks = (N_NODES + TB - 1) / TB;
    const int edge_blocks = (N_EDGES / EPT + TB - 1) / TB;

    k_init    <<<node_blocks, TB>>>();
    k_degree  <<<edge_blocks, TB>>>(col);
    k_layer1  <<<node_blocks, TB>>>(x, W1);
    k_scatter1<<<edge_blocks, TB>>>(row, col);
    k_layer2  <<<node_blocks, TB>>>(W2, b1);
    k_scatter2<<<edge_blocks, TB>>>(row, col);
    k_final   <<<node_blocks, TB>>>(out, b2);
}

// round 6
// speedup vs baseline: 1.0462x; 1.0462x over previous
#include <cuda_runtime.h>
#include <cstdint>

#define N_NODES 500000
#define N_EDGES 16000000

// ---------------- scratch (device globals; no allocation allowed) ----------
__device__ int    g_deg [N_NODES];
__device__ float  g_dinv[N_NODES];
__device__ float4 g_g1  [N_NODES];   // dinv-scaled layer-1 features
__device__ float4 g_S1  [N_NODES];   // layer-1 scatter accumulator
__device__ float2 g_g2  [N_NODES];   // dinv-scaled layer-2 features
__device__ float2 g_S2  [N_NODES];   // layer-2 scatter accumulator

// ---------------- vectorized L2 reductions (PTX ISA 8.1, sm_90+) -----------
__device__ __forceinline__ void red_add_v4(float4* addr, float4 v) {
    asm volatile("red.global.add.v4.f32 [%0], {%1, %2, %3, %4};"
                 :: "l"(addr), "f"(v.x), "f"(v.y), "f"(v.z), "f"(v.w)
                 : "memory");
}
__device__ __forceinline__ void red_add_v2(float2* addr, float2 v) {
    asm volatile("red.global.add.v2.f32 [%0], {%1, %2};"
                 :: "l"(addr), "f"(v.x), "f"(v.y)
                 : "memory");
}

// ---------------- kernels ---------------------------------------------------
// zero degrees only (S1/S2 zeroing folded into layer kernels)
__global__ void k_init_deg() {
    int i = blockIdx.x * blockDim.x + threadIdx.x;
    if (i < N_NODES) g_deg[i] = 0;
}

// degree from target (col) indices; 4 edges per thread via one 16B load
__global__ void __launch_bounds__(256) k_degree(const int* __restrict__ col) {
    int t = blockIdx.x * blockDim.x + threadIdx.x;
    int base = t * 4;
    if (base >= N_EDGES) return;
    int4 c = *reinterpret_cast<const int4*>(col + base);
    atomicAdd(&g_deg[c.x], 1);
    atomicAdd(&g_deg[c.y], 1);
    atomicAdd(&g_deg[c.z], 1);
    atomicAdd(&g_deg[c.w], 1);
}

// independent of degrees: h1 = x @ W1 (unscaled) -> g_g1; runs concurrent with k_degree
__global__ void k_matmul1(const float* __restrict__ x,
                          const float* __restrict__ W1) {
    int i = blockIdx.x * blockDim.x + threadIdx.x;
    if (i >= N_NODES) return;
    const float* xr = x + (long long)i * 9;
    float h0 = 0.f, h1 = 0.f, h2 = 0.f, h3 = 0.f;
#pragma unroll
    for (int k = 0; k < 9; ++k) {
        float xv = __ldg(xr + k);
        h0 += xv * __ldg(W1 + k * 4 + 0);
        h1 += xv * __ldg(W1 + k * 4 + 1);
        h2 += xv * __ldg(W1 + k * 4 + 2);
        h3 += xv * __ldg(W1 + k * 4 + 3);
    }
    g_g1[i] = make_float4(h0, h1, h2, h3);
}

// after degree+matmul: dinv, g1 *= dinv, zero S1
__global__ void k_scale1() {
    int i = blockIdx.x * blockDim.x + threadIdx.x;
    if (i >= N_NODES) return;
    float d = rsqrtf((float)g_deg[i] + 1.0f);
    g_dinv[i] = d;
    float4 h = g_g1[i];
    g_g1[i] = make_float4(h.x * d, h.y * d, h.z * d, h.w * d);
    g_S1[i] = make_float4(0.f, 0.f, 0.f, 0.f);
}

// layer-1 edge scatter: S1[col] += g1[row]   (one v4 red per edge)
__global__ void __launch_bounds__(256) k_scatter1(const int* __restrict__ row,
                                                  const int* __restrict__ col) {
    int t = blockIdx.x * blockDim.x + threadIdx.x;
    int base = t * 4;
    if (base >= N_EDGES) return;
    int4 r = *reinterpret_cast<const int4*>(row + base);
    int4 c = *reinterpret_cast<const int4*>(col + base);
    float4 v0 = __ldg(&g_g1[r.x]);
    float4 v1 = __ldg(&g_g1[r.y]);
    float4 v2 = __ldg(&g_g1[r.z]);
    float4 v3 = __ldg(&g_g1[r.w]);
    red_add_v4(&g_S1[c.x], v0);
    red_add_v4(&g_S1[c.y], v1);
    red_add_v4(&g_S1[c.z], v2);
    red_add_v4(&g_S1[c.w], v3);
}

// per-node: t = tanh(dinv*(S1+g1)+b1); h2 = t @ W2; g2 = h2 * dinv; zero S2
__global__ void k_layer2(const float* __restrict__ W2,
                         const float* __restrict__ b1) {
    int i = blockIdx.x * blockDim.x + threadIdx.x;
    if (i >= N_NODES) return;
    float d  = g_dinv[i];
    float4 s = g_S1[i];
    float4 g = g_g1[i];
    float t0 = tanhf(d * (s.x + g.x) + __ldg(b1 + 0));
    float t1 = tanhf(d * (s.y + g.y) + __ldg(b1 + 1));
    float t2 = tanhf(d * (s.z + g.z) + __ldg(b1 + 2));
    float t3 = tanhf(d * (s.w + g.w) + __ldg(b1 + 3));
    float u0 = t0 * __ldg(W2 + 0) + t1 * __ldg(W2 + 2) + t2 * __ldg(W2 + 4) + t3 * __ldg(W2 + 6);
    float u1 = t0 * __ldg(W2 + 1) + t1 * __ldg(W2 + 3) + t2 * __ldg(W2 + 5) + t3 * __ldg(W2 + 7);
    g_g2[i] = make_float2(u0 * d, u1 * d);
    g_S2[i] = make_float2(0.f, 0.f);
}

// layer-2 edge scatter: S2[col] += g2[row]   (one v2 red per edge)
__global__ void __launch_bounds__(256) k_scatter2(const int* __restrict__ row,
                                                  const int* __restrict__ col) {
    int t = blockIdx.x * blockDim.x + threadIdx.x;
    int base = t * 4;
    if (base >= N_EDGES) return;
    int4 r = *reinterpret_cast<const int4*>(row + base);
    int4 c = *reinterpret_cast<const int4*>(col + base);
    float2 v0 = __ldg(&g_g2[r.x]);
    float2 v1 = __ldg(&g_g2[r.y]);
    float2 v2 = __ldg(&g_g2[r.z]);
    float2 v3 = __ldg(&g_g2[r.w]);
    red_add_v2(&g_S2[c.x], v0);
    red_add_v2(&g_S2[c.y], v1);
    red_add_v2(&g_S2[c.z], v2);
    red_add_v2(&g_S2[c.w], v3);
}

// finalize: out = dinv*(S2+g2) + b2
__global__ void k_final(float2* __restrict__ out,
                        const float* __restrict__ b2) {
    int i = blockIdx.x * blockDim.x + threadIdx.x;
    if (i >= N_NODES) return;
    float d  = g_dinv[i];
    float2 s = g_S2[i];
    float2 g = g_g2[i];
    out[i] = make_float2(d * (s.x + g.x) + __ldg(b2 + 0),
                         d * (s.y + g.y) + __ldg(b2 + 1));
}

// ---------------- launch -----------------------------------------------------
extern "C" void kernel_launch(void* const* d_in, const int* in_sizes, int n_in,
                              void* d_out, int out_size) {
    const float* x  = (const float*)d_in[0];
    const int*   ei = (const int*)d_in[1];     // [2, 16M] int32 (JAX x64 disabled)
    const float* W1 = (const float*)d_in[2];   // [9,4]
    const float* b1 = (const float*)d_in[3];   // [4]
    const float* W2 = (const float*)d_in[4];   // [4,2]
    const float* b2 = (const float*)d_in[5];   // [2]
    float2*      out = (float2*)d_out;         // [N,2] f32

    const int* row = ei;
    const int* col = ei + N_EDGES;

    const int TB = 256;
    const int node_blocks = (N_NODES + TB - 1) / TB;
    const int edge_blocks = (N_EDGES / 4 + TB - 1) / TB;

    // side stream + events for degree/matmul overlap (created once; never freed
    // during the run — static lifetime, no device-memory allocation involved)
    static cudaStream_t s2 = nullptr;
    static cudaEvent_t ev_fork = nullptr, ev_join = nullptr;
    if (!s2) {
        cudaStreamCreateWithFlags(&s2, cudaStreamNonBlocking);
        cudaEventCreateWithFlags(&ev_fork, cudaEventDisableTiming);
        cudaEventCreateWithFlags(&ev_join, cudaEventDisableTiming);
    }

    // capture/main stream is the legacy default stream
    cudaStream_t s0 = (cudaStream_t)0;

    k_init_deg<<<node_blocks, TB, 0, s0>>>();

    // fork: matmul1 on s2 concurrent with degree on s0
    cudaEventRecord(ev_fork, s0);
    cudaStreamWaitEvent(s2, ev_fork, 0);
    k_matmul1<<<node_blocks, TB, 0, s2>>>(x, W1);
    cudaEventRecord(ev_join, s2);

    k_degree<<<edge_blocks, TB, 0, s0>>>(col);

    // join
    cudaStreamWaitEvent(s0, ev_join, 0);

    k_scale1  <<<node_blocks, TB, 0, s0>>>();
    k_scatter1<<<edge_blocks, TB, 0, s0>>>(row, col);
    k_layer2  <<<node_blocks, TB, 0, s0>>>(W2, b1);
    k_scatter2<<<edge_blocks, TB, 0, s0>>>(row, col);
    k_final   <<<node_blocks, TB, 0, s0>>>(out, b2);
}